// round 13
// baseline (speedup 1.0000x reference)
#include <cuda_runtime.h>
#include <cstdint>

#define NODE_DIM 64
#define MSG_DIM  64
#define PROP_DIM 32
#define HIDDEN   128
#define T_DIM    8
#define S_DIM    16

#define MAX_V    10000
#define GD 2             // groups per CTA iteration (duo)
#define FSTR 72          // fp32 floats per A row in smem: conflict-free LDS.64
#define GROUP_FLOATS (S_DIM * FSTR)   // 1152

// Scratch: base[v][h] = h_t[v].Wh + theta[v].Wp + b1
__device__ float g_base[MAX_V * HIDDEN];

// pack two fp32 -> fp16x2 (lo = first arg), round-to-nearest-even
__device__ __forceinline__ uint32_t pack_h2(float lo, float hi) {
    uint32_t r;
    asm("cvt.rn.f16x2.f32 %0, %1, %2;" : "=r"(r) : "f"(hi), "f"(lo));
    return r;
}

#define MMA_F16(D, a0, a1, a2, a3, b0, b1)                                    \
    asm volatile(                                                             \
        "mma.sync.aligned.m16n8k16.row.col.f32.f16.f16.f32 "                  \
        "{%0,%1,%2,%3}, {%4,%5,%6,%7}, {%8,%9}, {%0,%1,%2,%3};"               \
        : "+f"(D[0]), "+f"(D[1]), "+f"(D[2]), "+f"(D[3])                      \
        : "r"(a0), "r"(a1), "r"(a2), "r"(a3), "r"(b0), "r"(b1))

__device__ __forceinline__ void cp_async16(uint32_t dst_smem, const void* src) {
    asm volatile("cp.async.cg.shared.global [%0], [%1], 16;" :: "r"(dst_smem), "l"(src));
}

// ---------------------------------------------------------------------------
// Kernel 1 (tensorized, verified R12): base[v][h] = b1 + [h_t|theta][v] @ W_sub
// ---------------------------------------------------------------------------
__global__ __launch_bounds__(128) void base_mma_kernel(
    const float* __restrict__ h_t,
    const float* __restrict__ theta,
    const float* __restrict__ W1,
    const float* __restrict__ b1,
    int V)
{
    __shared__ uint32_t Asm[32 * 52];     // 6656 B
    __shared__ uint32_t Bts[128 * 52];    // 26624 B

    const int tid   = threadIdx.x;
    const int lane  = tid & 31;
    const int w     = tid >> 5;
    const int qd    = lane & 3;
    const int gq    = lane >> 2;
    const int chalf = w & 1;
    const int pl    = w >> 1;
    const int wbase = chalf * 64;
    const int v0    = blockIdx.x * 32;

    #pragma unroll 8
    for (int dp = 0; dp < 48; ++dp) {
        const int d0 = 2 * dp, d1 = 2 * dp + 1;
        const int r0 = d0 + ((d0 >> 6) * 65);
        const int r1 = d1 + ((d1 >> 6) * 65);
        float w0 = __ldg(&W1[r0 * HIDDEN + tid]);
        float w1 = __ldg(&W1[r1 * HIDDEN + tid]);
        Bts[tid * 52 + dp] = pack_h2(w0, w1);
    }

    #pragma unroll
    for (int i = 0; i < 4; ++i) {
        const int c = tid + i * 128;
        const int n = c >> 4, f4 = c & 15;
        int v = v0 + n; if (v > V - 1) v = V - 1;
        float4 x = __ldg((const float4*)&h_t[(size_t)v * NODE_DIM + f4 * 4]);
        Asm[n * 52 + f4 * 2]     = pack_h2(x.x, x.y);
        Asm[n * 52 + f4 * 2 + 1] = pack_h2(x.z, x.w);
    }
    #pragma unroll
    for (int i = 0; i < 2; ++i) {
        const int c = tid + i * 128;
        const int n = c >> 3, f4 = c & 7;
        int v = v0 + n; if (v > V - 1) v = V - 1;
        float4 x = __ldg((const float4*)&theta[(size_t)v * PROP_DIM + f4 * 4]);
        Asm[n * 52 + 32 + f4 * 2]     = pack_h2(x.x, x.y);
        Asm[n * 52 + 32 + f4 * 2 + 1] = pack_h2(x.z, x.w);
    }
    __syncthreads();

    float acc[8][4];
    #pragma unroll
    for (int nb = 0; nb < 8; ++nb)
        #pragma unroll
        for (int i = 0; i < 4; ++i) acc[nb][i] = 0.f;

    const uint32_t* Arow = Asm + (pl * 16) * 52;
    #pragma unroll
    for (int kk = 0; kk < 6; ++kk) {
        const int ko = kk * 8 + qd;
        uint32_t a0 = Arow[gq * 52 + ko];
        uint32_t a1 = Arow[(gq + 8) * 52 + ko];
        uint32_t a2 = Arow[gq * 52 + ko + 4];
        uint32_t a3 = Arow[(gq + 8) * 52 + ko + 4];
        #pragma unroll
        for (int nb = 0; nb < 8; ++nb) {
            const uint32_t* Bc = Bts + (wbase + nb * 8 + gq) * 52 + ko;
            MMA_F16(acc[nb], a0, a1, a2, a3, Bc[0], Bc[4]);
        }
    }

    const int r_lo = v0 + pl * 16 + gq;
    const int r_hi = r_lo + 8;
    #pragma unroll
    for (int nb = 0; nb < 8; ++nb) {
        const int c0 = wbase + nb * 8 + qd * 2;
        float2 bv = __ldg((const float2*)&b1[c0]);
        if (r_lo < V) {
            float2 o; o.x = acc[nb][0] + bv.x; o.y = acc[nb][1] + bv.y;
            *(float2*)&g_base[(size_t)r_lo * HIDDEN + c0] = o;
        }
        if (r_hi < V) {
            float2 o; o.x = acc[nb][2] + bv.x; o.y = acc[nb][3] + bv.y;
            *(float2*)&g_base[(size_t)r_hi * HIDDEN + c0] = o;
        }
    }
}

// ---------------------------------------------------------------------------
// Kernel 2: duo-tile (GD=2), 5 CTAs/SM. One group per warp-pair per iter.
// B fragments: kk 0-1 in registers (32 regs), kk 2-3 from lane-indexed smem.
// ---------------------------------------------------------------------------

__device__ __forceinline__ void stage_duo(
    float* Asb, float* bsb,
    const float* __restrict__ messages, int q, int tid)
{
    const float* msrc = messages + (size_t)q * (GD * S_DIM * MSG_DIM);
    #pragma unroll
    for (int i = 0; i < 4; ++i) {
        int c   = tid + i * 128;      // 16B chunk index, 0..511
        int grp = c >> 8;
        int m   = c & 255;
        int row = m >> 4;
        int cc  = m & 15;
        uint32_t dst = (uint32_t)__cvta_generic_to_shared(
            Asb + grp * GROUP_FLOATS + row * FSTR + cc * 4);
        cp_async16(dst, msrc + c * 4);
    }
    if (tid < 32) {
        int v = q >> 2;   // duo q covers groups 2q,2q+1 -> node = q/4
        uint32_t dst = (uint32_t)__cvta_generic_to_shared(bsb + tid * 4);
        cp_async16(dst, g_base + (size_t)v * HIDDEN + tid * 4);
    }
}

__global__ __launch_bounds__(128, 5) void main_kernel(
    const float* __restrict__ messages,
    const float* __restrict__ tau_values,
    const float* __restrict__ W1,
    const float* __restrict__ W2,
    const float* __restrict__ b2,
    float* __restrict__ out,
    int nGroups, int nDuos)
{
    __shared__ float As[2][GD * GROUP_FLOATS];       // 18432 B
    __shared__ float bsm[2][HIDDEN];                 // 1024 B
    __shared__ float red[2][GD][S_DIM][2];           // 1024 B
    __shared__ float taW[T_DIM][HIDDEN];             // 4096 B
    __shared__ float W2sm[HIDDEN];                   // 512 B
    __shared__ float addsm[GD][HIDDEN];              // 1024 B
    __shared__ uint32_t Bsm[2 * 8 * 2 * 2 * 32];     // 8192 B: [chalf][nb][kk-2][r][lane]

    const int tid   = threadIdx.x;
    const int lane  = tid & 31;
    const int w     = tid >> 5;
    const int qd    = lane & 3;
    const int gq    = lane >> 2;
    const int chalf = w & 1;           // column half
    const int jband = w >> 1;          // group of the duo owned by this pair
    const int wbase = chalf * 64;

    const int grid = gridDim.x;
    int q = blockIdx.x;   // clamped to nDuos

    stage_duo(As[0], bsm[0], messages, q, tid);
    asm volatile("cp.async.commit_group;");

    // --- B fragments kk 0-1 in regs (32), kk 2-3 into smem (lane-indexed) ---
    uint32_t bf[8][2][2];
    {
        const float* Wm = W1 + NODE_DIM * HIDDEN;
        #pragma unroll
        for (int nb = 0; nb < 8; ++nb) {
            const int col = wbase + nb * 8 + gq;
            #pragma unroll
            for (int kk = 0; kk < 2; ++kk) {
                const int kb = kk * 16 + 2 * qd;
                bf[nb][kk][0] = pack_h2(Wm[(kb)     * HIDDEN + col],
                                        Wm[(kb + 1) * HIDDEN + col]);
                bf[nb][kk][1] = pack_h2(Wm[(kb + 8) * HIDDEN + col],
                                        Wm[(kb + 9) * HIDDEN + col]);
            }
        }
        if (w < 2) {   // warp w fills chalf=w (warps 2,3 share the same data)
            const int cb = w * 64;
            #pragma unroll
            for (int nb = 0; nb < 8; ++nb) {
                const int col = cb + nb * 8 + gq;
                #pragma unroll
                for (int kk = 2; kk < 4; ++kk) {
                    const int kb = kk * 16 + 2 * qd;
                    uint32_t b0 = pack_h2(Wm[(kb)     * HIDDEN + col],
                                          Wm[(kb + 1) * HIDDEN + col]);
                    uint32_t b1 = pack_h2(Wm[(kb + 8) * HIDDEN + col],
                                          Wm[(kb + 9) * HIDDEN + col]);
                    const int ib = (((w * 8 + nb) * 2 + (kk - 2)) * 2) * 32 + lane;
                    Bsm[ib]      = b0;
                    Bsm[ib + 32] = b1;
                }
            }
        }
    }

    // --- Epilogue constants ---
    {
        const float* Wt = W1 + (NODE_DIM + MSG_DIM) * HIDDEN;
        float wt = Wt[tid];
        #pragma unroll
        for (int t = 0; t < T_DIM; ++t)
            taW[t][tid] = __ldg(&tau_values[t]) * wt;
        W2sm[tid] = W2[tid];
    }
    const float b2v = __ldg(&b2[0]);

    asm volatile("cp.async.wait_group 0;");
    __syncthreads();   // buf0 + Bsm + taW/W2sm visible

    const uint32_t* BsmW = Bsm + (chalf * 8) * 2 * 2 * 32 + lane;

    int cur = 0;
    for (;;) {
        const bool hasNext = (q + grid < nDuos);

        if (hasNext) {
            stage_duo(As[cur ^ 1], bsm[cur ^ 1], messages, q + grid, tid);
            asm volatile("cp.async.commit_group;");
        }

        const int g0 = q * GD;
        const int j  = jband;
        const int tj = (g0 + j) & (T_DIM - 1);

        // per-warp addsm for own group's own column half
        {
            const int col = wbase + lane * 2;
            float2 bv = *(const float2*)&bsm[cur][col];
            float2 tw = *(const float2*)&taW[tj][col];
            float2 ad;
            ad.x = bv.x + tw.x;
            ad.y = bv.y + tw.y;
            *(float2*)&addsm[j][col] = ad;
        }
        __syncwarp();

        // --- MMA on group j of buf[cur] ---
        const float* Ab = &As[cur][j * GROUP_FLOATS];

        float acc[8][4];
        #pragma unroll
        for (int nb = 0; nb < 8; ++nb)
            #pragma unroll
            for (int i = 0; i < 4; ++i) acc[nb][i] = 0.f;

        #pragma unroll
        for (int kk = 0; kk < 4; ++kk) {
            const float* Ak = Ab + kk * 16 + 2 * qd;
            float2 v0 = *(const float2*)&Ak[gq * FSTR];
            float2 v1 = *(const float2*)&Ak[(gq + 8) * FSTR];
            float2 v2 = *(const float2*)&Ak[gq * FSTR + 8];
            float2 v3 = *(const float2*)&Ak[(gq + 8) * FSTR + 8];
            uint32_t a0 = pack_h2(v0.x, v0.y);
            uint32_t a1 = pack_h2(v1.x, v1.y);
            uint32_t a2 = pack_h2(v2.x, v2.y);
            uint32_t a3 = pack_h2(v3.x, v3.y);
            if (kk < 2) {
                #pragma unroll
                for (int nb = 0; nb < 8; ++nb)
                    MMA_F16(acc[nb], a0, a1, a2, a3, bf[nb][kk][0], bf[nb][kk][1]);
            } else {
                #pragma unroll
                for (int nb = 0; nb < 8; ++nb) {
                    const uint32_t* Bc = BsmW + ((nb * 2 + (kk - 2)) * 2) * 32;
                    MMA_F16(acc[nb], a0, a1, a2, a3, Bc[0], Bc[32]);
                }
            }
        }

        // --- Lean epilogue ---
        const float* adj = addsm[j];
        float pl0 = 0.f, pl1 = 0.f, ph0 = 0.f, ph1 = 0.f;
        #pragma unroll
        for (int nb = 0; nb < 8; ++nb) {
            const int c0 = wbase + nb * 8 + qd * 2;
            float2 ad = *(const float2*)&adj[c0];
            float2 w2 = *(const float2*)&W2sm[c0];
            if (nb & 1) {
                pl1 = fmaf(fmaxf(acc[nb][0] + ad.x, 0.f), w2.x, pl1);
                pl1 = fmaf(fmaxf(acc[nb][1] + ad.y, 0.f), w2.y, pl1);
                ph1 = fmaf(fmaxf(acc[nb][2] + ad.x, 0.f), w2.x, ph1);
                ph1 = fmaf(fmaxf(acc[nb][3] + ad.y, 0.f), w2.y, ph1);
            } else {
                pl0 = fmaf(fmaxf(acc[nb][0] + ad.x, 0.f), w2.x, pl0);
                pl0 = fmaf(fmaxf(acc[nb][1] + ad.y, 0.f), w2.y, pl0);
                ph0 = fmaf(fmaxf(acc[nb][2] + ad.x, 0.f), w2.x, ph0);
                ph0 = fmaf(fmaxf(acc[nb][3] + ad.y, 0.f), w2.y, ph0);
            }
        }
        float ps_lo = pl0 + pl1;
        float ps_hi = ph0 + ph1;
        ps_lo += __shfl_xor_sync(0xffffffffu, ps_lo, 1);
        ps_lo += __shfl_xor_sync(0xffffffffu, ps_lo, 2);
        ps_hi += __shfl_xor_sync(0xffffffffu, ps_hi, 1);
        ps_hi += __shfl_xor_sync(0xffffffffu, ps_hi, 2);
        if (qd == 0) {
            red[cur][j][gq][chalf]     = ps_lo;
            red[cur][j][gq + 8][chalf] = ps_hi;
        }

        if (hasNext) asm volatile("cp.async.wait_group 0;");
        __syncthreads();   // buf[cur^1] staged AND red[cur] ready

        if (tid < GD * S_DIM) {
            const int jo  = tid >> 4;
            const int row = tid & 15;
            const int g   = g0 + jo;
            if (g < nGroups)
                out[(size_t)g * S_DIM + row] =
                    red[cur][jo][row][0] + red[cur][jo][row][1] + b2v;
        }

        if (!hasNext) break;
        cur ^= 1;
        q += grid;
    }
}

// ---------------------------------------------------------------------------
extern "C" void kernel_launch(void* const* d_in, const int* in_sizes, int n_in,
                              void* d_out, int out_size)
{
    const float* h_t      = (const float*)d_in[0];
    const float* messages = (const float*)d_in[1];
    const float* tau      = (const float*)d_in[2];
    const float* theta    = (const float*)d_in[3];
    const float* W1       = (const float*)d_in[4];
    const float* b1       = (const float*)d_in[5];
    const float* W2       = (const float*)d_in[6];
    const float* b2       = (const float*)d_in[7];
    float* out = (float*)d_out;

    const int V = in_sizes[0] / NODE_DIM;
    const int nGroups = V * T_DIM;
    const int nDuos   = nGroups / GD;

    base_mma_kernel<<<(V + 31) / 32, 128>>>(h_t, theta, W1, b1, V);

    int nb_occ = 0, nsm = 148;
    cudaOccupancyMaxActiveBlocksPerMultiprocessor(&nb_occ, main_kernel, 128, 0);
    cudaDeviceGetAttribute(&nsm, cudaDevAttrMultiProcessorCount, 0);
    if (nb_occ < 1) nb_occ = 5;
    int grid = nb_occ * nsm;
    if (grid > nDuos) grid = nDuos;

    main_kernel<<<grid, 128>>>(messages, tau, W1, W2, b2, out, nGroups, nDuos);
}

// round 14
// speedup vs baseline: 1.1446x; 1.1446x over previous
#include <cuda_runtime.h>
#include <cstdint>

#define NODE_DIM 64
#define MSG_DIM  64
#define PROP_DIM 32
#define HIDDEN   128
#define T_DIM    8
#define S_DIM    16

#define MAX_V    10000
#define GQ 4             // groups per CTA iteration (quad) — R12 proven
#define FSTR 72          // fp32 floats per A row in smem: conflict-free LDS.64
#define GROUP_FLOATS (S_DIM * FSTR)   // 1152

// Scratch: base[v][h] = h_t[v].Wh + theta[v].Wp + b1
__device__ float g_base[MAX_V * HIDDEN];

// pack two fp32 -> fp16x2 (lo = first arg), round-to-nearest-even
__device__ __forceinline__ uint32_t pack_h2(float lo, float hi) {
    uint32_t r;
    asm("cvt.rn.f16x2.f32 %0, %1, %2;" : "=r"(r) : "f"(hi), "f"(lo));
    return r;
}

#define MMA_F16(D, a0, a1, a2, a3, b0, b1)                                    \
    asm volatile(                                                             \
        "mma.sync.aligned.m16n8k16.row.col.f32.f16.f16.f32 "                  \
        "{%0,%1,%2,%3}, {%4,%5,%6,%7}, {%8,%9}, {%0,%1,%2,%3};"               \
        : "+f"(D[0]), "+f"(D[1]), "+f"(D[2]), "+f"(D[3])                      \
        : "r"(a0), "r"(a1), "r"(a2), "r"(a3), "r"(b0), "r"(b1))

__device__ __forceinline__ void cp_async16(uint32_t dst_smem, const void* src) {
    asm volatile("cp.async.cg.shared.global [%0], [%1], 16;" :: "r"(dst_smem), "l"(src));
}

// ---------------------------------------------------------------------------
// Kernel 1 (tensorized, verified R12): base[v][h] = b1 + [h_t|theta][v] @ W_sub
// ---------------------------------------------------------------------------
__global__ __launch_bounds__(128) void base_mma_kernel(
    const float* __restrict__ h_t,
    const float* __restrict__ theta,
    const float* __restrict__ W1,
    const float* __restrict__ b1,
    int V)
{
    __shared__ uint32_t Asm[32 * 52];     // 6656 B
    __shared__ uint32_t Bts[128 * 52];    // 26624 B

    const int tid   = threadIdx.x;
    const int lane  = tid & 31;
    const int w     = tid >> 5;
    const int qd    = lane & 3;
    const int gq    = lane >> 2;
    const int chalf = w & 1;
    const int pl    = w >> 1;
    const int wbase = chalf * 64;
    const int v0    = blockIdx.x * 32;

    #pragma unroll 8
    for (int dp = 0; dp < 48; ++dp) {
        const int d0 = 2 * dp, d1 = 2 * dp + 1;
        const int r0 = d0 + ((d0 >> 6) * 65);
        const int r1 = d1 + ((d1 >> 6) * 65);
        float w0 = __ldg(&W1[r0 * HIDDEN + tid]);
        float w1 = __ldg(&W1[r1 * HIDDEN + tid]);
        Bts[tid * 52 + dp] = pack_h2(w0, w1);
    }

    #pragma unroll
    for (int i = 0; i < 4; ++i) {
        const int c = tid + i * 128;
        const int n = c >> 4, f4 = c & 15;
        int v = v0 + n; if (v > V - 1) v = V - 1;
        float4 x = __ldg((const float4*)&h_t[(size_t)v * NODE_DIM + f4 * 4]);
        Asm[n * 52 + f4 * 2]     = pack_h2(x.x, x.y);
        Asm[n * 52 + f4 * 2 + 1] = pack_h2(x.z, x.w);
    }
    #pragma unroll
    for (int i = 0; i < 2; ++i) {
        const int c = tid + i * 128;
        const int n = c >> 3, f4 = c & 7;
        int v = v0 + n; if (v > V - 1) v = V - 1;
        float4 x = __ldg((const float4*)&theta[(size_t)v * PROP_DIM + f4 * 4]);
        Asm[n * 52 + 32 + f4 * 2]     = pack_h2(x.x, x.y);
        Asm[n * 52 + 32 + f4 * 2 + 1] = pack_h2(x.z, x.w);
    }
    __syncthreads();

    float acc[8][4];
    #pragma unroll
    for (int nb = 0; nb < 8; ++nb)
        #pragma unroll
        for (int i = 0; i < 4; ++i) acc[nb][i] = 0.f;

    const uint32_t* Arow = Asm + (pl * 16) * 52;
    #pragma unroll
    for (int kk = 0; kk < 6; ++kk) {
        const int ko = kk * 8 + qd;
        uint32_t a0 = Arow[gq * 52 + ko];
        uint32_t a1 = Arow[(gq + 8) * 52 + ko];
        uint32_t a2 = Arow[gq * 52 + ko + 4];
        uint32_t a3 = Arow[(gq + 8) * 52 + ko + 4];
        #pragma unroll
        for (int nb = 0; nb < 8; ++nb) {
            const uint32_t* Bc = Bts + (wbase + nb * 8 + gq) * 52 + ko;
            MMA_F16(acc[nb], a0, a1, a2, a3, Bc[0], Bc[4]);
        }
    }

    const int r_lo = v0 + pl * 16 + gq;
    const int r_hi = r_lo + 8;
    #pragma unroll
    for (int nb = 0; nb < 8; ++nb) {
        const int c0 = wbase + nb * 8 + qd * 2;
        float2 bv = __ldg((const float2*)&b1[c0]);
        if (r_lo < V) {
            float2 o; o.x = acc[nb][0] + bv.x; o.y = acc[nb][1] + bv.y;
            *(float2*)&g_base[(size_t)r_lo * HIDDEN + c0] = o;
        }
        if (r_hi < V) {
            float2 o; o.x = acc[nb][2] + bv.x; o.y = acc[nb][3] + bv.y;
            *(float2*)&g_base[(size_t)r_hi * HIDDEN + c0] = o;
        }
    }
}

// ---------------------------------------------------------------------------
// Kernel 2: R12 quad-tile structure; bias folded into MMA accumulator init.
// acc[nb] starts at base[c]+tau*Wt[c] -> epilogue is just relu * W2.
// ---------------------------------------------------------------------------

__device__ __forceinline__ void stage_quad(
    float* Asb, float* bsb,
    const float* __restrict__ messages, int q, int tid)
{
    const float* msrc = messages + (size_t)q * (GQ * S_DIM * MSG_DIM);
    #pragma unroll
    for (int i = 0; i < 8; ++i) {
        int c   = tid + i * 128;      // 16B chunk index, 0..1023
        int grp = c >> 8;
        int m   = c & 255;
        int row = m >> 4;
        int cc  = m & 15;
        uint32_t dst = (uint32_t)__cvta_generic_to_shared(
            Asb + grp * GROUP_FLOATS + row * FSTR + cc * 4);
        cp_async16(dst, msrc + c * 4);
    }
    if (tid < 32) {
        int v = q >> 1;   // quad q -> node q/2
        uint32_t dst = (uint32_t)__cvta_generic_to_shared(bsb + tid * 4);
        cp_async16(dst, g_base + (size_t)v * HIDDEN + tid * 4);
    }
}

__global__ __launch_bounds__(128, 4) void main_kernel(
    const float* __restrict__ messages,
    const float* __restrict__ tau_values,
    const float* __restrict__ W1,
    const float* __restrict__ W2,
    const float* __restrict__ b2,
    float* __restrict__ out,
    int nGroups, int nQuads)
{
    __shared__ float As[2][GQ * GROUP_FLOATS];       // 36864 B
    __shared__ float bsm[2][HIDDEN];                 // 1024 B
    __shared__ float red[2][GQ][S_DIM][2];           // 1024 B
    __shared__ float taW[T_DIM][HIDDEN];             // 4096 B
    __shared__ float W2sm[HIDDEN];                   // 512 B

    const int tid   = threadIdx.x;
    const int lane  = tid & 31;
    const int w     = tid >> 5;
    const int qd    = lane & 3;
    const int gq    = lane >> 2;
    const int chalf = w & 1;
    const int jband = w >> 1;
    const int wbase = chalf * 64;

    const int grid = gridDim.x;
    int q = blockIdx.x;

    stage_quad(As[0], bsm[0], messages, q, tid);
    asm volatile("cp.async.commit_group;");

    // --- Persistent B fragments (fp16x2): 8 n-blocks of this warp's half ---
    uint32_t bf[8][4][2];
    {
        const float* Wm = W1 + NODE_DIM * HIDDEN;
        #pragma unroll
        for (int nb = 0; nb < 8; ++nb) {
            const int col = wbase + nb * 8 + gq;
            #pragma unroll
            for (int kk = 0; kk < 4; ++kk) {
                const int kb = kk * 16 + 2 * qd;
                bf[nb][kk][0] = pack_h2(Wm[(kb)     * HIDDEN + col],
                                        Wm[(kb + 1) * HIDDEN + col]);
                bf[nb][kk][1] = pack_h2(Wm[(kb + 8) * HIDDEN + col],
                                        Wm[(kb + 9) * HIDDEN + col]);
            }
        }
    }

    // --- Epilogue constants ---
    {
        const float* Wt = W1 + (NODE_DIM + MSG_DIM) * HIDDEN;
        float wt = Wt[tid];
        #pragma unroll
        for (int t = 0; t < T_DIM; ++t)
            taW[t][tid] = __ldg(&tau_values[t]) * wt;
        W2sm[tid] = W2[tid];
    }
    const float b2v = __ldg(&b2[0]);

    asm volatile("cp.async.wait_group 0;");
    __syncthreads();

    int cur = 0;
    for (;;) {
        const bool hasNext = (q + grid < nQuads);

        if (hasNext) {
            stage_quad(As[cur ^ 1], bsm[cur ^ 1], messages, q + grid, tid);
            asm volatile("cp.async.commit_group;");
        }

        const int g0 = q * GQ;
        const int t0 = g0 & (T_DIM - 1);
        const float* bcur = bsm[cur];

        #pragma unroll
        for (int jj = 0; jj < 2; ++jj) {
            const int j = jband + 2 * jj;
            const float* Ab = &As[cur][j * GROUP_FLOATS];
            const float* taWj = taW[t0 + j];

            // acc init = base + tau*Wt (bias folded into MMA C-operand)
            float acc[8][4];
            #pragma unroll
            for (int nb = 0; nb < 8; ++nb) {
                const int c0 = wbase + nb * 8 + qd * 2;
                float2 bv = *(const float2*)&bcur[c0];
                float2 tw = *(const float2*)&taWj[c0];
                acc[nb][0] = bv.x + tw.x;
                acc[nb][1] = bv.y + tw.y;
                acc[nb][2] = acc[nb][0];
                acc[nb][3] = acc[nb][1];
            }

            #pragma unroll
            for (int kk = 0; kk < 4; ++kk) {
                const float* Ak = Ab + kk * 16 + 2 * qd;
                float2 v0 = *(const float2*)&Ak[gq * FSTR];
                float2 v1 = *(const float2*)&Ak[(gq + 8) * FSTR];
                float2 v2 = *(const float2*)&Ak[gq * FSTR + 8];
                float2 v3 = *(const float2*)&Ak[(gq + 8) * FSTR + 8];
                uint32_t a0 = pack_h2(v0.x, v0.y);
                uint32_t a1 = pack_h2(v1.x, v1.y);
                uint32_t a2 = pack_h2(v2.x, v2.y);
                uint32_t a3 = pack_h2(v3.x, v3.y);
                #pragma unroll
                for (int nb = 0; nb < 8; ++nb)
                    MMA_F16(acc[nb], a0, a1, a2, a3, bf[nb][kk][0], bf[nb][kk][1]);
            }

            // Epilogue: relu * W2 only (bias already inside acc)
            float pl0 = 0.f, pl1 = 0.f, ph0 = 0.f, ph1 = 0.f;
            #pragma unroll
            for (int nb = 0; nb < 8; ++nb) {
                const int c0 = wbase + nb * 8 + qd * 2;
                float2 w2 = *(const float2*)&W2sm[c0];
                if (nb & 1) {
                    pl1 = fmaf(fmaxf(acc[nb][0], 0.f), w2.x, pl1);
                    pl1 = fmaf(fmaxf(acc[nb][1], 0.f), w2.y, pl1);
                    ph1 = fmaf(fmaxf(acc[nb][2], 0.f), w2.x, ph1);
                    ph1 = fmaf(fmaxf(acc[nb][3], 0.f), w2.y, ph1);
                } else {
                    pl0 = fmaf(fmaxf(acc[nb][0], 0.f), w2.x, pl0);
                    pl0 = fmaf(fmaxf(acc[nb][1], 0.f), w2.y, pl0);
                    ph0 = fmaf(fmaxf(acc[nb][2], 0.f), w2.x, ph0);
                    ph0 = fmaf(fmaxf(acc[nb][3], 0.f), w2.y, ph0);
                }
            }
            float ps_lo = pl0 + pl1;
            float ps_hi = ph0 + ph1;
            ps_lo += __shfl_xor_sync(0xffffffffu, ps_lo, 1);
            ps_lo += __shfl_xor_sync(0xffffffffu, ps_lo, 2);
            ps_hi += __shfl_xor_sync(0xffffffffu, ps_hi, 1);
            ps_hi += __shfl_xor_sync(0xffffffffu, ps_hi, 2);
            if (qd == 0) {
                red[cur][j][gq][chalf]     = ps_lo;
                red[cur][j][gq + 8][chalf] = ps_hi;
            }
        }

        if (hasNext) asm volatile("cp.async.wait_group 0;");
        __syncthreads();   // buf[cur^1] staged AND red[cur] ready

        if (tid < GQ * S_DIM) {
            const int j   = tid >> 4;
            const int row = tid & 15;
            const int g   = g0 + j;
            if (g < nGroups)
                out[(size_t)g * S_DIM + row] =
                    red[cur][j][row][0] + red[cur][j][row][1] + b2v;
        }

        if (!hasNext) break;
        cur ^= 1;
        q += grid;
    }
}

// ---------------------------------------------------------------------------
extern "C" void kernel_launch(void* const* d_in, const int* in_sizes, int n_in,
                              void* d_out, int out_size)
{
    const float* h_t      = (const float*)d_in[0];
    const float* messages = (const float*)d_in[1];
    const float* tau      = (const float*)d_in[2];
    const float* theta    = (const float*)d_in[3];
    const float* W1       = (const float*)d_in[4];
    const float* b1       = (const float*)d_in[5];
    const float* W2       = (const float*)d_in[6];
    const float* b2       = (const float*)d_in[7];
    float* out = (float*)d_out;

    const int V = in_sizes[0] / NODE_DIM;
    const int nGroups = V * T_DIM;
    const int nQuads  = nGroups / GQ;

    base_mma_kernel<<<(V + 31) / 32, 128>>>(h_t, theta, W1, b1, V);

    int nb_occ = 0, nsm = 148;
    cudaOccupancyMaxActiveBlocksPerMultiprocessor(&nb_occ, main_kernel, 128, 0);
    cudaDeviceGetAttribute(&nsm, cudaDevAttrMultiProcessorCount, 0);
    if (nb_occ < 1) nb_occ = 4;
    int grid = nb_occ * nsm;
    if (grid > nQuads) grid = nQuads;

    main_kernel<<<grid, 128>>>(messages, tau, W1, W2, b2, out, nGroups, nQuads);
}